// round 6
// baseline (speedup 1.0000x reference)
#include <cuda_runtime.h>
#include <cstdint>

#define TT     48000
#define NCH    512
#define NW     10                  // warps per block
#define NTHR   (NW * 32)           // 320
#define LCH    16                  // samples per lane per tile (64B chunks)
#define TILE   (NTHR * LCH)        // 5120
#define NTILE  ((TT + TILE - 1) / TILE)   // 10 (last tile partial: 1920 = 120 lanes)

#define FULLM 0xffffffffu

// 2x2 matrix multiply: O = A * B
#define MM(o00,o01,o10,o11, a00,a01,a10,a11, b00,b01,b10,b11) do { \
    float t00 = a00*b00 + a01*b10; \
    float t01 = a00*b01 + a01*b11; \
    float t10 = a10*b00 + a11*b10; \
    float t11 = a10*b01 + a11*b11; \
    o00=t00; o01=t01; o10=t10; o11=t11; } while(0)

__global__ __launch_bounds__(NTHR, 3) void biquad_kernel(
    const float* __restrict__ x,
    const float* __restrict__ b0v, const float* __restrict__ b1v,
    const float* __restrict__ b2v, const float* __restrict__ a1v,
    const float* __restrict__ a2v, float* __restrict__ y)
{
    __shared__ float sP[5 * 4];               // P[k] = Q^(2^k)
    __shared__ float sT1[2][NW], sT2[2][NW];  // per-warp tile totals, parity-buffered

    const int ch   = blockIdx.x;
    const int tid  = threadIdx.x;
    const int lane = tid & 31;
    const int w    = tid >> 5;

    const float B0 = b0v[ch], B1 = b1v[ch], B2 = b2v[ch];
    const float A1 = a1v[ch], A2 = a2v[ch];
    const float nA1 = -A1, nA2 = -A2;

    // y-state transition: s[n] = (y[n], y[n-1]), s' = My s + (f,0),
    // My = [[-A1,-A2],[1,0]]. Q = My^LCH; P[k] = Q^(2^k); W = Q^32 = My^(32*LCH).
    float p00[5], p01[5], p10[5], p11[5];
    {
        float m00 = nA1, m01 = nA2, m10 = 1.f, m11 = 0.f;
        float r00 = 1.f, r01 = 0.f, r10 = 0.f, r11 = 1.f;
        int e = LCH;
        while (e) {
            if (e & 1) { MM(r00,r01,r10,r11, r00,r01,r10,r11, m00,m01,m10,m11); }
            e >>= 1;
            if (e) { MM(m00,m01,m10,m11, m00,m01,m10,m11, m00,m01,m10,m11); }
        }
        p00[0] = r00; p01[0] = r01; p10[0] = r10; p11[0] = r11;
        #pragma unroll
        for (int k = 1; k < 5; ++k) {
            MM(p00[k],p01[k],p10[k],p11[k],
               p00[k-1],p01[k-1],p10[k-1],p11[k-1],
               p00[k-1],p01[k-1],p10[k-1],p11[k-1]);
        }
    }
    float W00, W01, W10, W11;  // Q^32
    MM(W00,W01,W10,W11, p00[4],p01[4],p10[4],p11[4], p00[4],p01[4],p10[4],p11[4]);

    // Qlane = Q^lane
    float q00 = 1.f, q01 = 0.f, q10 = 0.f, q11 = 1.f;
    #pragma unroll
    for (int k = 0; k < 5; ++k) {
        if ((lane >> k) & 1) {
            MM(q00,q01,q10,q11, p00[k],p01[k],p10[k],p11[k], q00,q01,q10,q11);
        }
    }
    if (tid == 0) {
        #pragma unroll
        for (int k = 0; k < 5; ++k) {
            sP[k*4+0] = p00[k]; sP[k*4+1] = p01[k];
            sP[k*4+2] = p10[k]; sP[k*4+3] = p11[k];
        }
    }
    __syncthreads();

    const float* __restrict__ xg = x + (size_t)ch * TT;
    float* __restrict__       yg = y + (size_t)ch * TT;

    float carry1 = 0.f, carry2 = 0.f;   // (y[-1], y[-2]) entering tile; identical in all threads

    for (int t = 0; t < NTILE; ++t) {
        const int gb = t * TILE + (w * 32 + lane) * LCH;   // chunk start within channel
        const bool valid = gb < TT;    // whole lane chunk in/out (tail splits on lane boundary)

        // ---- load 16 x into registers (4x LDG.128) ----
        float xr[LCH];
        if (valid) {
            const float4* p4 = (const float4*)(xg + gb);
            float4 a = __ldg(p4 + 0), b = __ldg(p4 + 1);
            float4 c = __ldg(p4 + 2), d = __ldg(p4 + 3);
            xr[0]=a.x;  xr[1]=a.y;  xr[2]=a.z;  xr[3]=a.w;
            xr[4]=b.x;  xr[5]=b.y;  xr[6]=b.z;  xr[7]=b.w;
            xr[8]=c.x;  xr[9]=c.y;  xr[10]=c.z; xr[11]=c.w;
            xr[12]=d.x; xr[13]=d.y; xr[14]=d.z; xr[15]=d.w;
        } else {
            #pragma unroll
            for (int k = 0; k < LCH; ++k) xr[k] = 0.f;
        }

        // ---- x lookback: previous lane's last two samples via shuffle ----
        float up1 = __shfl_up_sync(FULLM, xr[15], 1);
        float up2 = __shfl_up_sync(FULLM, xr[14], 1);
        float xm1, xm2;
        if (lane == 0) {
            xm1 = (valid && gb >= 1) ? __ldg(xg + gb - 1) : 0.f;
            xm2 = (valid && gb >= 2) ? __ldg(xg + gb - 2) : 0.f;
        } else {
            xm1 = up1; xm2 = up2;
        }

        // ---- pass 1: compute feedforward f in place + zero-state y end values ----
        float y1 = 0.f, y2 = 0.f;
        #pragma unroll
        for (int k = 0; k < LCH; ++k) {
            float v = xr[k];
            float f = fmaf(B0, v, fmaf(B1, xm1, B2 * xm2));
            xr[k] = f;                                   // x dead after this
            float yn = fmaf(nA1, y1, fmaf(nA2, y2, f));
            y2 = y1; y1 = yn; xm2 = xm1; xm1 = v;
        }

        // ---- warp inclusive affine scan of (y1,y2) chunk end states ----
        float E1 = y1, E2 = y2;
        #pragma unroll
        for (int k = 0; k < 5; ++k) {
            const int d = 1 << k;
            float u1 = __shfl_up_sync(FULLM, E1, d);
            float u2 = __shfl_up_sync(FULLM, E2, d);
            float a = sP[k*4+0], b = sP[k*4+1], c = sP[k*4+2], dd = sP[k*4+3];
            if (lane >= d) {
                E1 = fmaf(a, u1, fmaf(b, u2, E1));
                E2 = fmaf(c, u1, fmaf(dd, u2, E2));
            }
        }
        if (lane == 31) { sT1[t & 1][w] = E1; sT2[t & 1][w] = E2; }
        __syncthreads();   // one block barrier per tile

        // ---- cross-warp combine (redundant in every thread; 10 links) ----
        float c1 = carry1, c2 = carry2;
        float wc1 = 0.f, wc2 = 0.f;   // state entering this warp's slice
        #pragma unroll
        for (int i = 0; i < NW; ++i) {
            if (i == w) { wc1 = c1; wc2 = c2; }
            float e1 = sT1[t & 1][i], e2 = sT2[t & 1][i];
            float n1 = fmaf(W00, c1, fmaf(W01, c2, e1));
            float n2 = fmaf(W10, c1, fmaf(W11, c2, e2));
            c1 = n1; c2 = n2;
        }
        carry1 = c1; carry2 = c2;

        // ---- true start state for this lane: S = Q^lane * wc + E_exclusive ----
        float Ex1 = __shfl_up_sync(FULLM, E1, 1);
        float Ex2 = __shfl_up_sync(FULLM, E2, 1);
        if (lane == 0) { Ex1 = 0.f; Ex2 = 0.f; }
        float ym1 = q00 * wc1 + q01 * wc2 + Ex1;   // y[start-1]
        float ym2 = q10 * wc1 + q11 * wc2 + Ex2;   // y[start-2]

        // ---- pass 2: y[n] = f[n] - a1 y[n-1] - a2 y[n-2]; store regs->gmem ----
        float4* const o4 = (float4*)(yg + gb);
        #pragma unroll
        for (int g = 0; g < LCH / 4; ++g) {
            float4 o;
            { float yn = fmaf(nA1, ym1, fmaf(nA2, ym2, xr[g*4+0])); ym2 = ym1; ym1 = yn; o.x = yn; }
            { float yn = fmaf(nA1, ym1, fmaf(nA2, ym2, xr[g*4+1])); ym2 = ym1; ym1 = yn; o.y = yn; }
            { float yn = fmaf(nA1, ym1, fmaf(nA2, ym2, xr[g*4+2])); ym2 = ym1; ym1 = yn; o.z = yn; }
            { float yn = fmaf(nA1, ym1, fmaf(nA2, ym2, xr[g*4+3])); ym2 = ym1; ym1 = yn; o.w = yn; }
            if (valid) o4[g] = o;
        }
    }
}

extern "C" void kernel_launch(void* const* d_in, const int* in_sizes, int n_in,
                              void* d_out, int out_size)
{
    const float* x  = (const float*)d_in[0];
    const float* b0 = (const float*)d_in[1];
    const float* b1 = (const float*)d_in[2];
    const float* b2 = (const float*)d_in[3];
    const float* a1 = (const float*)d_in[4];
    const float* a2 = (const float*)d_in[5];
    float* yo = (float*)d_out;

    biquad_kernel<<<NCH, NTHR>>>(x, b0, b1, b2, a1, a2, yo);
}

// round 7
// speedup vs baseline: 1.3497x; 1.3497x over previous
#include <cuda_runtime.h>
#include <cstdint>

#define TT     48000
#define NCH    512
#define NW     10                 // warps per block
#define NTHR   (NW * 32)          // 320
#define LCH    25                 // samples per lane per tile (odd -> conflict-free LDS/STS)
#define WSLICE (32 * LCH)         // 800 samples per warp per tile
#define TILE   (NW * WSLICE)      // 8000
#define NTILE  (TT / TILE)        // 6 (exact)

#define XS_BYTES (NW * 2 * WSLICE * 4)   // 64000B dynamic smem

#define FULLM 0xffffffffu

// 2x2 matrix multiply: O = A * B
#define MM(o00,o01,o10,o11, a00,a01,a10,a11, b00,b01,b10,b11) do { \
    float t00 = a00*b00 + a01*b10; \
    float t01 = a00*b01 + a01*b11; \
    float t10 = a10*b00 + a11*b10; \
    float t11 = a10*b01 + a11*b11; \
    o00=t00; o01=t01; o10=t10; o11=t11; } while(0)

__device__ __forceinline__ uint32_t s2u(const void* p) {
    return (uint32_t)__cvta_generic_to_shared(p);
}
__device__ __forceinline__ void cp_async16(uint32_t saddr, const void* gaddr) {
    asm volatile("cp.async.cg.shared.global [%0], [%1], 16;"
                 :: "r"(saddr), "l"(gaddr) : "memory");
}
__device__ __forceinline__ void cp_commit() {
    asm volatile("cp.async.commit_group;" ::: "memory");
}
template<int N> __device__ __forceinline__ void cp_wait() {
    asm volatile("cp.async.wait_group %0;" :: "n"(N) : "memory");
}

__global__ __launch_bounds__(NTHR, 3) void biquad_kernel(
    const float* __restrict__ x,
    const float* __restrict__ b0v, const float* __restrict__ b1v,
    const float* __restrict__ b2v, const float* __restrict__ a1v,
    const float* __restrict__ a2v, float* __restrict__ y)
{
    extern __shared__ __align__(16) float xs[];   // NW * 2 * WSLICE floats
    __shared__ float sP[5 * 4];                   // P[k] = Q^(2^k)
    __shared__ float sT1[2][NW], sT2[2][NW];      // per-warp tile totals, parity-buffered

    const int ch   = blockIdx.x;
    const int tid  = threadIdx.x;
    const int lane = tid & 31;
    const int w    = tid >> 5;

    const float B0 = b0v[ch], B1 = b1v[ch], B2 = b2v[ch];
    const float A1 = a1v[ch], A2 = a2v[ch];
    const float nA1 = -A1, nA2 = -A2;

    // y-state transition: s[n] = (y[n], y[n-1]), s' = My s + (f,0),
    // My = [[-A1,-A2],[1,0]]. Q = My^LCH; P[k] = Q^(2^k); W = Q^32 = My^WSLICE.
    float p00[5], p01[5], p10[5], p11[5];
    {
        float m00 = nA1, m01 = nA2, m10 = 1.f, m11 = 0.f;
        float r00 = 1.f, r01 = 0.f, r10 = 0.f, r11 = 1.f;
        int e = LCH;
        while (e) {
            if (e & 1) { MM(r00,r01,r10,r11, r00,r01,r10,r11, m00,m01,m10,m11); }
            e >>= 1;
            if (e) { MM(m00,m01,m10,m11, m00,m01,m10,m11, m00,m01,m10,m11); }
        }
        p00[0] = r00; p01[0] = r01; p10[0] = r10; p11[0] = r11;
        #pragma unroll
        for (int k = 1; k < 5; ++k) {
            MM(p00[k],p01[k],p10[k],p11[k],
               p00[k-1],p01[k-1],p10[k-1],p11[k-1],
               p00[k-1],p01[k-1],p10[k-1],p11[k-1]);
        }
    }
    float W00, W01, W10, W11;  // Q^32
    MM(W00,W01,W10,W11, p00[4],p01[4],p10[4],p11[4], p00[4],p01[4],p10[4],p11[4]);

    // Qlane = Q^lane
    float q00 = 1.f, q01 = 0.f, q10 = 0.f, q11 = 1.f;
    #pragma unroll
    for (int k = 0; k < 5; ++k) {
        if ((lane >> k) & 1) {
            MM(q00,q01,q10,q11, p00[k],p01[k],p10[k],p11[k], q00,q01,q10,q11);
        }
    }
    if (tid == 0) {
        #pragma unroll
        for (int k = 0; k < 5; ++k) {
            sP[k*4+0] = p00[k]; sP[k*4+1] = p01[k];
            sP[k*4+2] = p10[k]; sP[k*4+3] = p11[k];
        }
    }
    __syncthreads();

    const float* __restrict__ xg = x + (size_t)ch * TT;
    float* __restrict__       yg = y + (size_t)ch * TT;
    float* const buf0 = xs + w * (2 * WSLICE);

    // Prefetch tile 0 (this warp's slice only)
    {
        const float* src = xg + w * WSLICE;
        uint32_t dst = s2u(buf0);
        #pragma unroll
        for (int i = lane; i < WSLICE / 4; i += 32)
            cp_async16(dst + i * 16, src + i * 4);
        cp_commit();
    }

    float carry1 = 0.f, carry2 = 0.f;   // (y[-1], y[-2]) entering tile; identical in all threads

    for (int t = 0; t < NTILE; ++t) {
        float* const buf = buf0 + (t & 1) * WSLICE;

        if (t + 1 < NTILE) {
            const float* src = xg + (t + 1) * TILE + w * WSLICE;
            uint32_t dst = s2u(buf0 + ((t + 1) & 1) * WSLICE);
            #pragma unroll
            for (int i = lane; i < WSLICE / 4; i += 32)
                cp_async16(dst + i * 16, src + i * 4);
            cp_commit();
            cp_wait<1>();
        } else {
            cp_wait<0>();
        }
        __syncwarp();

        float* const xc = buf + lane * LCH;

        // ---- x lookback (read before anything overwrites this tile's buffer) ----
        float xm1, xm2;
        if (lane == 0) {
            const int g = t * TILE + w * WSLICE;
            xm1 = (g >= 1) ? __ldg(xg + g - 1) : 0.f;
            xm2 = (g >= 2) ? __ldg(xg + g - 2) : 0.f;
        } else {
            xm1 = xc[-1];
            xm2 = xc[-2];
        }

        // ---- pass 1: feedforward f into registers + zero-state recurrence ----
        float f[LCH];
        float y1 = 0.f, y2 = 0.f;
        #pragma unroll
        for (int k = 0; k < LCH; ++k) {
            float v = xc[k];
            float fk = fmaf(B0, v, fmaf(B1, xm1, B2 * xm2));
            f[k] = fk;
            float yn = fmaf(nA1, y1, fmaf(nA2, y2, fk));
            y2 = y1; y1 = yn; xm2 = xm1; xm1 = v;
        }

        // ---- warp inclusive affine scan of (y1,y2) chunk end states ----
        float E1 = y1, E2 = y2;
        #pragma unroll
        for (int k = 0; k < 5; ++k) {
            const int d = 1 << k;
            float u1 = __shfl_up_sync(FULLM, E1, d);
            float u2 = __shfl_up_sync(FULLM, E2, d);
            float a = sP[k*4+0], b = sP[k*4+1], c = sP[k*4+2], dd = sP[k*4+3];
            if (lane >= d) {
                E1 = fmaf(a, u1, fmaf(b, u2, E1));
                E2 = fmaf(c, u1, fmaf(dd, u2, E2));
            }
        }
        if (lane == 31) { sT1[t & 1][w] = E1; sT2[t & 1][w] = E2; }
        __syncthreads();   // one block barrier per tile

        // ---- cross-warp combine (redundant in every thread; 10 links) ----
        float c1 = carry1, c2 = carry2;
        float wc1 = 0.f, wc2 = 0.f;
        #pragma unroll
        for (int i = 0; i < NW; ++i) {
            if (i == w) { wc1 = c1; wc2 = c2; }
            float e1 = sT1[t & 1][i], e2 = sT2[t & 1][i];
            float n1 = fmaf(W00, c1, fmaf(W01, c2, e1));
            float n2 = fmaf(W10, c1, fmaf(W11, c2, e2));
            c1 = n1; c2 = n2;
        }
        carry1 = c1; carry2 = c2;

        // ---- true start state for this lane: S = Q^lane * wc + E_exclusive ----
        float Ex1 = __shfl_up_sync(FULLM, E1, 1);
        float Ex2 = __shfl_up_sync(FULLM, E2, 1);
        if (lane == 0) { Ex1 = 0.f; Ex2 = 0.f; }
        float ym1 = q00 * wc1 + q01 * wc2 + Ex1;   // y[start-1]
        float ym2 = q10 * wc1 + q11 * wc2 + Ex2;   // y[start-2]

        // ---- pass 2: y[n] = f[n] - a1 y[n-1] - a2 y[n-2]; STS back to buffer ----
        #pragma unroll
        for (int k = 0; k < LCH; ++k) {
            float yn = fmaf(nA1, ym1, fmaf(nA2, ym2, f[k]));
            ym2 = ym1; ym1 = yn;
            xc[k] = yn;
        }
        __syncwarp();

        // ---- coalesced float4 store of this warp's slice ----
        float4* const yg4 = (float4*)(yg + t * TILE + w * WSLICE);
        const float4* const b4 = (const float4*)buf;
        #pragma unroll
        for (int i = lane; i < WSLICE / 4; i += 32)
            yg4[i] = b4[i];
        // next cp.async into this buffer: same lane writes exactly the float4
        // slots it just read here (per-lane program order), and all other-lane
        // STS into it were ordered by the __syncwarp above.
    }
}

extern "C" void kernel_launch(void* const* d_in, const int* in_sizes, int n_in,
                              void* d_out, int out_size)
{
    const float* x  = (const float*)d_in[0];
    const float* b0 = (const float*)d_in[1];
    const float* b1 = (const float*)d_in[2];
    const float* b2 = (const float*)d_in[3];
    const float* a1 = (const float*)d_in[4];
    const float* a2 = (const float*)d_in[5];
    float* yo = (float*)d_out;

    static int smem_set = 0;
    if (!smem_set) {
        cudaFuncSetAttribute(biquad_kernel,
                             cudaFuncAttributeMaxDynamicSharedMemorySize, XS_BYTES);
        smem_set = 1;
    }
    biquad_kernel<<<NCH, NTHR, XS_BYTES>>>(x, b0, b1, b2, a1, a2, yo);
}

// round 8
// speedup vs baseline: 1.4386x; 1.0659x over previous
#include <cuda_runtime.h>
#include <cstdint>

#define TT     48000
#define NCH    512
#define NW     10                 // warps per block
#define NTHR   (NW * 32)          // 320
#define LCH    15                 // samples per lane per tile (odd -> conflict-free LDS)
#define WSLICE (32 * LCH)         // 480 samples per warp per tile
#define TILE   (NW * WSLICE)      // 4800
#define NTILE  (TT / TILE)        // 10 (exact)

#define FULLM 0xffffffffu

// 2x2 matrix multiply: O = A * B
#define MM(o00,o01,o10,o11, a00,a01,a10,a11, b00,b01,b10,b11) do { \
    float t00 = a00*b00 + a01*b10; \
    float t01 = a00*b01 + a01*b11; \
    float t10 = a10*b00 + a11*b10; \
    float t11 = a10*b01 + a11*b11; \
    o00=t00; o01=t01; o10=t10; o11=t11; } while(0)

__device__ __forceinline__ uint32_t s2u(const void* p) {
    return (uint32_t)__cvta_generic_to_shared(p);
}
__device__ __forceinline__ void cp_async16(uint32_t saddr, const void* gaddr) {
    asm volatile("cp.async.cg.shared.global [%0], [%1], 16;"
                 :: "r"(saddr), "l"(gaddr) : "memory");
}
__device__ __forceinline__ void cp_commit() {
    asm volatile("cp.async.commit_group;" ::: "memory");
}
template<int N> __device__ __forceinline__ void cp_wait() {
    asm volatile("cp.async.wait_group %0;" :: "n"(N) : "memory");
}

__global__ __launch_bounds__(NTHR, 4) void biquad_kernel(
    const float* __restrict__ x,
    const float* __restrict__ b0v, const float* __restrict__ b1v,
    const float* __restrict__ b2v, const float* __restrict__ a1v,
    const float* __restrict__ a2v, float* __restrict__ y)
{
    __shared__ __align__(16) float xs[NW * 2 * WSLICE];  // 38400 B
    __shared__ float sP[5 * 4];                   // P[k] = Q^(2^k)
    __shared__ float sT1[2][NW], sT2[2][NW];      // per-warp tile totals, parity-buffered

    const int ch   = blockIdx.x;
    const int tid  = threadIdx.x;
    const int lane = tid & 31;
    const int w    = tid >> 5;

    const float B0 = b0v[ch], B1 = b1v[ch], B2 = b2v[ch];
    const float A1 = a1v[ch], A2 = a2v[ch];
    const float nA1 = -A1, nA2 = -A2;

    // y-state transition: s[n] = (y[n], y[n-1]), s' = My s + (f,0),
    // My = [[-A1,-A2],[1,0]]. Q = My^LCH; P[k] = Q^(2^k); W = Q^32 = My^WSLICE.
    float p00[5], p01[5], p10[5], p11[5];
    {
        float m00 = nA1, m01 = nA2, m10 = 1.f, m11 = 0.f;
        float r00 = 1.f, r01 = 0.f, r10 = 0.f, r11 = 1.f;
        int e = LCH;
        while (e) {
            if (e & 1) { MM(r00,r01,r10,r11, r00,r01,r10,r11, m00,m01,m10,m11); }
            e >>= 1;
            if (e) { MM(m00,m01,m10,m11, m00,m01,m10,m11, m00,m01,m10,m11); }
        }
        p00[0] = r00; p01[0] = r01; p10[0] = r10; p11[0] = r11;
        #pragma unroll
        for (int k = 1; k < 5; ++k) {
            MM(p00[k],p01[k],p10[k],p11[k],
               p00[k-1],p01[k-1],p10[k-1],p11[k-1],
               p00[k-1],p01[k-1],p10[k-1],p11[k-1]);
        }
    }
    float W00, W01, W10, W11;  // Q^32
    MM(W00,W01,W10,W11, p00[4],p01[4],p10[4],p11[4], p00[4],p01[4],p10[4],p11[4]);

    // Qlane = Q^lane
    float q00 = 1.f, q01 = 0.f, q10 = 0.f, q11 = 1.f;
    #pragma unroll
    for (int k = 0; k < 5; ++k) {
        if ((lane >> k) & 1) {
            MM(q00,q01,q10,q11, p00[k],p01[k],p10[k],p11[k], q00,q01,q10,q11);
        }
    }
    if (tid == 0) {
        #pragma unroll
        for (int k = 0; k < 5; ++k) {
            sP[k*4+0] = p00[k]; sP[k*4+1] = p01[k];
            sP[k*4+2] = p10[k]; sP[k*4+3] = p11[k];
        }
    }
    __syncthreads();

    const float* __restrict__ xg = x + (size_t)ch * TT;
    float* __restrict__       yg = y + (size_t)ch * TT;
    float* const buf0 = xs + w * (2 * WSLICE);

    // Prefetch tile 0 (this warp's slice only)
    {
        const float* src = xg + w * WSLICE;
        uint32_t dst = s2u(buf0);
        #pragma unroll
        for (int i = lane; i < WSLICE / 4; i += 32)
            cp_async16(dst + i * 16, src + i * 4);
        cp_commit();
    }

    float carry1 = 0.f, carry2 = 0.f;   // (y[-1], y[-2]) entering tile; identical in all threads

    for (int t = 0; t < NTILE; ++t) {
        float* const buf = buf0 + (t & 1) * WSLICE;

        if (t + 1 < NTILE) {
            const float* src = xg + (t + 1) * TILE + w * WSLICE;
            uint32_t dst = s2u(buf0 + ((t + 1) & 1) * WSLICE);
            #pragma unroll
            for (int i = lane; i < WSLICE / 4; i += 32)
                cp_async16(dst + i * 16, src + i * 4);
            cp_commit();
            cp_wait<1>();
        } else {
            cp_wait<0>();
        }
        __syncwarp();

        float* const xc = buf + lane * LCH;

        // ---- x lookback ----
        float xm1, xm2;
        if (lane == 0) {
            const int g = t * TILE + w * WSLICE;
            xm1 = (g >= 1) ? __ldg(xg + g - 1) : 0.f;
            xm2 = (g >= 2) ? __ldg(xg + g - 2) : 0.f;
        } else {
            xm1 = xc[-1];
            xm2 = xc[-2];
        }

        // ---- pass 1: feedforward f into registers + zero-state recurrence ----
        float f[LCH];
        float y1 = 0.f, y2 = 0.f;
        #pragma unroll
        for (int k = 0; k < LCH; ++k) {
            float v = xc[k];
            float fk = fmaf(B0, v, fmaf(B1, xm1, B2 * xm2));
            f[k] = fk;
            float yn = fmaf(nA1, y1, fmaf(nA2, y2, fk));
            y2 = y1; y1 = yn; xm2 = xm1; xm1 = v;
        }

        // ---- warp inclusive affine scan of (y1,y2) chunk end states ----
        float E1 = y1, E2 = y2;
        #pragma unroll
        for (int k = 0; k < 5; ++k) {
            const int d = 1 << k;
            float u1 = __shfl_up_sync(FULLM, E1, d);
            float u2 = __shfl_up_sync(FULLM, E2, d);
            float a = sP[k*4+0], b = sP[k*4+1], c = sP[k*4+2], dd = sP[k*4+3];
            if (lane >= d) {
                E1 = fmaf(a, u1, fmaf(b, u2, E1));
                E2 = fmaf(c, u1, fmaf(dd, u2, E2));
            }
        }
        if (lane == 31) { sT1[t & 1][w] = E1; sT2[t & 1][w] = E2; }
        __syncthreads();   // one block barrier per tile

        // ---- cross-warp combine (redundant in every thread; 10 links) ----
        float c1 = carry1, c2 = carry2;
        float wc1 = 0.f, wc2 = 0.f;
        #pragma unroll
        for (int i = 0; i < NW; ++i) {
            if (i == w) { wc1 = c1; wc2 = c2; }
            float e1 = sT1[t & 1][i], e2 = sT2[t & 1][i];
            float n1 = fmaf(W00, c1, fmaf(W01, c2, e1));
            float n2 = fmaf(W10, c1, fmaf(W11, c2, e2));
            c1 = n1; c2 = n2;
        }
        carry1 = c1; carry2 = c2;

        // ---- true start state for this lane: S = Q^lane * wc + E_exclusive ----
        float Ex1 = __shfl_up_sync(FULLM, E1, 1);
        float Ex2 = __shfl_up_sync(FULLM, E2, 1);
        if (lane == 0) { Ex1 = 0.f; Ex2 = 0.f; }
        float ym1 = q00 * wc1 + q01 * wc2 + Ex1;   // y[start-1]
        float ym2 = q10 * wc1 + q11 * wc2 + Ex2;   // y[start-2]

        // ---- pass 2: y[n] = f[n] - a1 y[n-1] - a2 y[n-2]; STS into buffer ----
        #pragma unroll
        for (int k = 0; k < LCH; ++k) {
            float yn = fmaf(nA1, ym1, fmaf(nA2, ym2, f[k]));
            ym2 = ym1; ym1 = yn;
            xc[k] = yn;
        }
        __syncwarp();

        // ---- coalesced float4 store of this warp's slice ----
        float4* const yg4 = (float4*)(yg + t * TILE + w * WSLICE);
        const float4* const b4 = (const float4*)buf;
        #pragma unroll
        for (int i = lane; i < WSLICE / 4; i += 32)
            yg4[i] = b4[i];
        // next cp.async into this buffer: same lane rewrites exactly the float4
        // slots it just read (per-lane program order); other lanes' STS were
        // ordered by the __syncwarp above.
    }
}

extern "C" void kernel_launch(void* const* d_in, const int* in_sizes, int n_in,
                              void* d_out, int out_size)
{
    const float* x  = (const float*)d_in[0];
    const float* b0 = (const float*)d_in[1];
    const float* b1 = (const float*)d_in[2];
    const float* b2 = (const float*)d_in[3];
    const float* a1 = (const float*)d_in[4];
    const float* a2 = (const float*)d_in[5];
    float* yo = (float*)d_out;

    biquad_kernel<<<NCH, NTHR>>>(x, b0, b1, b2, a1, a2, yo);
}